// round 3
// baseline (speedup 1.0000x reference)
#include <cuda_runtime.h>
#include <math.h>

// ---------------- problem constants ----------------
#define B_      8
#define FM      28
#define CH      384
#define IMG     448
#define NGROUP  3
#define NPROP   7          // 2 + 3 + 2
#define NTOT    1595       // 625 + 529 + 441

__device__ __constant__ int   c_n[NGROUP]       = {25, 23, 21};   // FM - r + 1
__device__ __constant__ int   c_ng[NGROUP]      = {625, 529, 441};
__device__ __constant__ int   c_off[NGROUP]     = {0, 625, 1154};
__device__ __constant__ int   c_r[NGROUP]       = {4, 6, 8};
__device__ __constant__ int   c_nsel[NGROUP]    = {2, 3, 2};
__device__ __constant__ int   c_colbase[NGROUP] = {0, 2, 5};

// output layout (all float32, tuple order flattened)
#define OFF_IDX  0
#define OFF_PSC  (OFF_IDX + B_ * NPROP)                   // 56
#define OFF_ALL  (OFF_PSC + B_ * NPROP)                   // 112
#define OFF_IMG  (OFF_ALL + B_ * NTOT)                    // 12872
#define OFF_LOG  (OFF_IMG + B_ * NPROP * 3 * IMG * IMG)   // 33731144

// scratch: selected global window indices per (batch, proposal-col)
__device__ int g_sel[B_ * NPROP];

// ---------------------------------------------------------------------------
// Kernel A: channel-sum -> 2D inclusive prefix (SAT) -> all window scores
// grid = B_, block = 1024
// ---------------------------------------------------------------------------
__global__ void scores_kernel(const float* __restrict__ fm, float* __restrict__ out)
{
    __shared__ float s[FM * FM];
    const int b   = blockIdx.x;
    const int tid = threadIdx.x;

    if (tid < FM * FM) {
        const float* p = fm + (size_t)b * CH * FM * FM + tid;
        float acc = 0.f;
        #pragma unroll 8
        for (int c = 0; c < CH; ++c) acc += p[c * FM * FM];
        s[tid] = acc;
    }
    __syncthreads();

    // row-wise inclusive prefix
    if (tid < FM) {
        float a = 0.f;
        for (int j = 0; j < FM; ++j) { a += s[tid * FM + j]; s[tid * FM + j] = a; }
    }
    __syncthreads();
    // column-wise inclusive prefix -> full SAT
    if (tid < FM) {
        float a = 0.f;
        for (int i = 0; i < FM; ++i) { a += s[i * FM + tid]; s[i * FM + tid] = a; }
    }
    __syncthreads();

    float* dst = out + OFF_ALL + b * NTOT;
    for (int t = tid; t < NTOT; t += blockDim.x) {
        int g = (t < 625) ? 0 : (t < 1154 ? 1 : 2);
        int l = t - c_off[g];
        int n = c_n[g], r = c_r[g];
        int i = l / n, j = l % n;
        int i2 = i + r - 1, j2 = j + r - 1;
        float sum = s[i2 * FM + j2];
        if (i > 0)          sum -= s[(i - 1) * FM + j2];
        if (j > 0)          sum -= s[i2 * FM + (j - 1)];
        if (i > 0 && j > 0) sum += s[(i - 1) * FM + (j - 1)];
        dst[t] = sum / (float)(r * r);
    }
}

// ---------------------------------------------------------------------------
// Kernel B: greedy IoU NMS per (batch, group). grid = B_*3, block = 256.
// Reads all_scores from d_out (written by kernel A), writes indices (as f32),
// gathered scores, and g_sel scratch.
// ---------------------------------------------------------------------------
__global__ void nms_kernel(float* __restrict__ out)
{
    const int blk = blockIdx.x;
    const int b = blk / NGROUP, g = blk % NGROUP;
    const int n = c_n[g], ng = c_ng[g], off = c_off[g];
    const int r = c_r[g], nsel = c_nsel[g], colbase = c_colbase[g];
    const int tid = threadIdx.x;
    const float NEG = -__int_as_float(0x7f800000);  // -inf

    __shared__ float sc[625];
    __shared__ float rv[256];
    __shared__ int   ri[256];
    __shared__ int   sel;

    const float* all = out + OFF_ALL + b * NTOT + off;
    for (int t = tid; t < ng; t += 256) sc[t] = all[t];
    __syncthreads();

    const float area = (16.f * r + 1.f) * (16.f * r + 1.f);
    const float side = 16.f * r;

    for (int k = 0; k < nsel; ++k) {
        // argmax (first occurrence on ties)
        float bv = NEG; int bi = 0x7fffffff;
        for (int t = tid; t < ng; t += 256) {
            float v = sc[t];
            if (v > bv) { bv = v; bi = t; }
        }
        rv[tid] = bv; ri[tid] = bi;
        __syncthreads();
        for (int st = 128; st > 0; st >>= 1) {
            if (tid < st) {
                float v = rv[tid + st]; int ii = ri[tid + st];
                if (v > rv[tid] || (v == rv[tid] && ii < ri[tid])) { rv[tid] = v; ri[tid] = ii; }
            }
            __syncthreads();
        }
        if (tid == 0) sel = ri[0];
        __syncthreads();
        const int si = sel;

        const float sx0 = (float)((si / n) * 16), sy0 = (float)((si % n) * 16);
        const float sx1 = sx0 + side, sy1 = sy0 + side;

        for (int t = tid; t < ng; t += 256) {
            float x0 = (float)((t / n) * 16), y0 = (float)((t % n) * 16);
            float x1 = x0 + side, y1 = y0 + side;
            float xx0 = fmaxf(x0, sx0), yy0 = fmaxf(y0, sy0);
            float xx1 = fminf(x1, sx1), yy1 = fminf(y1, sy1);
            float w = xx1 - xx0 + 1.f, h = yy1 - yy0 + 1.f;
            float inter = (w < 0.f || h < 0.f) ? 0.f : w * h;
            float iou = inter / (2.f * area - inter);
            if (iou > 0.25f) sc[t] = NEG;
        }
        __syncthreads();

        if (tid == 0) {
            int gi = off + si;
            out[OFF_IDX + b * NPROP + colbase + k] = (float)gi;
            out[OFF_PSC + b * NPROP + colbase + k] = all[si];
            g_sel[b * NPROP + colbase + k] = gi;
        }
        __syncthreads();
    }
}

// ---------------------------------------------------------------------------
// Kernel C: crop + bilinear resize to 448x448 (half-pixel, clamp-to-edge).
// grid = (784, 3, 56), block = 256. One thread per output pixel.
// ---------------------------------------------------------------------------
__global__ void crop_kernel(const float* __restrict__ x,
                            const int* __restrict__ coords,
                            float* __restrict__ out)
{
    const int p  = blockIdx.z;           // proposal 0..55  (= b*7 + col)
    const int ch = blockIdx.y;
    const int t  = blockIdx.x * blockDim.x + threadIdx.x;  // 0..200703
    const int oi = t / IMG, oj = t % IMG;

    const int col = p % NPROP;
    const int b   = p / NPROP;
    const int w   = (col < 2) ? 64 : ((col < 5) ? 96 : 128);

    const int gi = g_sel[p];
    const int c0 = __ldg(&coords[4 * gi + 0]);
    const int c1 = __ldg(&coords[4 * gi + 1]);

    const float scale = (float)w / (float)IMG;
    float ui = ((float)oi + 0.5f) * scale - 0.5f;
    float uj = ((float)oj + 0.5f) * scale - 0.5f;
    ui = fminf(fmaxf(ui, 0.f), (float)(w - 1));
    uj = fminf(fmaxf(uj, 0.f), (float)(w - 1));

    const int i0 = (int)ui, j0 = (int)uj;           // floor (non-negative)
    const int i1 = min(i0 + 1, w - 1), j1 = min(j0 + 1, w - 1);
    const float fi = ui - (float)i0, fj = uj - (float)j0;

    const float* src = x + (((size_t)b * 3 + ch) * IMG + c0) * IMG + c1;
    const float p00 = __ldg(&src[i0 * IMG + j0]);
    const float p01 = __ldg(&src[i0 * IMG + j1]);
    const float p10 = __ldg(&src[i1 * IMG + j0]);
    const float p11 = __ldg(&src[i1 * IMG + j1]);

    const float v = (1.f - fi) * ((1.f - fj) * p00 + fj * p01)
                  +        fi  * ((1.f - fj) * p10 + fj * p11);

    out[OFF_IMG + (((size_t)p * 3 + ch) * IMG + oi) * IMG + oj] = v;
}

// ---------------------------------------------------------------------------
// Kernel D: raw_logits = embedding @ W_cls + b_cls.  grid = B_, block = 200.
// Coalesced W row reads; e[k] broadcast from L1.
// ---------------------------------------------------------------------------
__global__ void logits_kernel(const float* __restrict__ emb,
                              const float* __restrict__ W,
                              const float* __restrict__ bias,
                              float* __restrict__ out)
{
    const int b = blockIdx.x;
    const int o = threadIdx.x;  // 0..199
    const float* e = emb + b * 2048;
    float a = 0.f;
    #pragma unroll 4
    for (int k = 0; k < 2048; ++k)
        a = fmaf(e[k], __ldg(&W[k * 200 + o]), a);
    out[OFF_LOG + b * 200 + o] = a + bias[o];
}

// ---------------------------------------------------------------------------
extern "C" void kernel_launch(void* const* d_in, const int* in_sizes, int n_in,
                              void* d_out, int out_size)
{
    const float* x      = (const float*)d_in[0];   // (8,3,448,448)
    const float* fm     = (const float*)d_in[1];   // (8,384,28,28)
    const float* emb    = (const float*)d_in[2];   // (8,2048)
    const float* W_cls  = (const float*)d_in[3];   // (2048,200)
    const float* b_cls  = (const float*)d_in[4];   // (200,)
    const int*   coords = (const int*)  d_in[5];   // (1595,4)
    float* out = (float*)d_out;

    scores_kernel<<<B_, 1024>>>(fm, out);
    nms_kernel<<<B_ * NGROUP, 256>>>(out);
    crop_kernel<<<dim3(IMG * IMG / 256, 3, B_ * NPROP), 256>>>(x, coords, out);
    logits_kernel<<<B_, 200>>>(emb, W_cls, b_cls, out);
}

// round 4
// speedup vs baseline: 3.6190x; 3.6190x over previous
#include <cuda_runtime.h>
#include <math.h>

// ---------------- problem constants ----------------
#define B_      8
#define FM      28
#define CH      384
#define IMG     448
#define NGROUP  3
#define NPROP   7          // 2 + 3 + 2
#define NTOT    1595       // 625 + 529 + 441

__device__ __constant__ int   c_n[NGROUP]       = {25, 23, 21};   // FM - r + 1
__device__ __constant__ int   c_ng[NGROUP]      = {625, 529, 441};
__device__ __constant__ int   c_off[NGROUP]     = {0, 625, 1154};
__device__ __constant__ int   c_r[NGROUP]       = {4, 6, 8};
__device__ __constant__ int   c_nsel[NGROUP]    = {2, 3, 2};
__device__ __constant__ int   c_colbase[NGROUP] = {0, 2, 5};

// output layout (all float32, tuple order flattened)
#define OFF_IDX  0
#define OFF_PSC  (OFF_IDX + B_ * NPROP)                   // 56
#define OFF_ALL  (OFF_PSC + B_ * NPROP)                   // 112
#define OFF_IMG  (OFF_ALL + B_ * NTOT)                    // 12872
#define OFF_LOG  (OFF_IMG + B_ * NPROP * 3 * IMG * IMG)   // 33731144

// scratch
__device__ int   g_sel[B_ * NPROP];
__device__ float g_csum[B_ * 8 * FM * FM];   // per-(batch, channel-slice) partial sums

// ---------------------------------------------------------------------------
// Kernel A1: channel-sum partials. grid=(B_, 8), block=784.
// Slice y sums channels [y*48, y*48+48) for every spatial position.
// ---------------------------------------------------------------------------
__global__ void csum_kernel(const float* __restrict__ fm)
{
    const int b = blockIdx.x, s = blockIdx.y;
    const int tid = threadIdx.x;                 // 0..783
    const float* p = fm + ((size_t)b * CH + s * 48) * (FM * FM) + tid;
    float acc = 0.f;
    #pragma unroll 8
    for (int c = 0; c < 48; ++c) acc += __ldg(&p[c * FM * FM]);
    g_csum[(b * 8 + s) * (FM * FM) + tid] = acc;
}

// ---------------------------------------------------------------------------
// Kernel A2: combine partials -> SAT -> all window scores. grid=B_, block=1024.
// ---------------------------------------------------------------------------
__global__ void scores_kernel(float* __restrict__ out)
{
    __shared__ float s[FM * FM];
    const int b   = blockIdx.x;
    const int tid = threadIdx.x;

    if (tid < FM * FM) {
        float a = 0.f;
        #pragma unroll
        for (int sl = 0; sl < 8; ++sl) a += g_csum[(b * 8 + sl) * (FM * FM) + tid];
        s[tid] = a;
    }
    __syncthreads();

    if (tid < FM) {                                  // row prefix
        float a = 0.f;
        for (int j = 0; j < FM; ++j) { a += s[tid * FM + j]; s[tid * FM + j] = a; }
    }
    __syncthreads();
    if (tid < FM) {                                  // column prefix -> SAT
        float a = 0.f;
        for (int i = 0; i < FM; ++i) { a += s[i * FM + tid]; s[i * FM + tid] = a; }
    }
    __syncthreads();

    float* dst = out + OFF_ALL + b * NTOT;
    for (int t = tid; t < NTOT; t += blockDim.x) {
        int g = (t < 625) ? 0 : (t < 1154 ? 1 : 2);
        int l = t - c_off[g];
        int n = c_n[g], r = c_r[g];
        int i = l / n, j = l % n;
        int i2 = i + r - 1, j2 = j + r - 1;
        float sum = s[i2 * FM + j2];
        if (i > 0)          sum -= s[(i - 1) * FM + j2];
        if (j > 0)          sum -= s[i2 * FM + (j - 1)];
        if (i > 0 && j > 0) sum += s[(i - 1) * FM + (j - 1)];
        dst[t] = sum / (float)(r * r);
    }
}

// ---------------------------------------------------------------------------
// Kernel B: greedy IoU NMS per (batch, group). grid = B_*3, block = 256.
// ---------------------------------------------------------------------------
__global__ void nms_kernel(float* __restrict__ out)
{
    const int blk = blockIdx.x;
    const int b = blk / NGROUP, g = blk % NGROUP;
    const int n = c_n[g], ng = c_ng[g], off = c_off[g];
    const int r = c_r[g], nsel = c_nsel[g], colbase = c_colbase[g];
    const int tid = threadIdx.x;
    const float NEG = -__int_as_float(0x7f800000);  // -inf

    __shared__ float sc[625];
    __shared__ float rv[256];
    __shared__ int   ri[256];
    __shared__ int   sel;

    const float* all = out + OFF_ALL + b * NTOT + off;
    for (int t = tid; t < ng; t += 256) sc[t] = all[t];
    __syncthreads();

    const float area = (16.f * r + 1.f) * (16.f * r + 1.f);
    const float side = 16.f * r;

    for (int k = 0; k < nsel; ++k) {
        float bv = NEG; int bi = 0x7fffffff;
        for (int t = tid; t < ng; t += 256) {
            float v = sc[t];
            if (v > bv) { bv = v; bi = t; }
        }
        rv[tid] = bv; ri[tid] = bi;
        __syncthreads();
        for (int st = 128; st > 0; st >>= 1) {
            if (tid < st) {
                float v = rv[tid + st]; int ii = ri[tid + st];
                if (v > rv[tid] || (v == rv[tid] && ii < ri[tid])) { rv[tid] = v; ri[tid] = ii; }
            }
            __syncthreads();
        }
        if (tid == 0) sel = ri[0];
        __syncthreads();
        const int si = sel;

        const float sx0 = (float)((si / n) * 16), sy0 = (float)((si % n) * 16);
        const float sx1 = sx0 + side, sy1 = sy0 + side;

        for (int t = tid; t < ng; t += 256) {
            float x0 = (float)((t / n) * 16), y0 = (float)((t % n) * 16);
            float x1 = x0 + side, y1 = y0 + side;
            float xx0 = fmaxf(x0, sx0), yy0 = fmaxf(y0, sy0);
            float xx1 = fminf(x1, sx1), yy1 = fminf(y1, sy1);
            float w = xx1 - xx0 + 1.f, h = yy1 - yy0 + 1.f;
            float inter = (w < 0.f || h < 0.f) ? 0.f : w * h;
            float iou = inter / (2.f * area - inter);
            if (iou > 0.25f) sc[t] = NEG;
        }
        __syncthreads();

        if (tid == 0) {
            int gi = off + si;
            out[OFF_IDX + b * NPROP + colbase + k] = (float)gi;
            out[OFF_PSC + b * NPROP + colbase + k] = all[si];
            g_sel[b * NPROP + colbase + k] = gi;
        }
        __syncthreads();
    }
}

// ---------------------------------------------------------------------------
// Kernel C: crop + bilinear resize, float4 stores (4 output px / thread).
// grid = (196, 3, 56), block = 256.
// ---------------------------------------------------------------------------
__global__ void crop_kernel(const float* __restrict__ x,
                            const int* __restrict__ coords,
                            float* __restrict__ out)
{
    const int p  = blockIdx.z;                                   // 0..55
    const int ch = blockIdx.y;
    const int t  = blockIdx.x * blockDim.x + threadIdx.x;        // 0..50175
    const int oi  = t / 112;
    const int oj0 = (t % 112) * 4;

    const int col = p % NPROP;
    const int b   = p / NPROP;
    const int w   = (col < 2) ? 64 : ((col < 5) ? 96 : 128);

    const int gi = g_sel[p];
    const int c0 = __ldg(&coords[4 * gi + 0]);
    const int c1 = __ldg(&coords[4 * gi + 1]);

    const float scale = (float)w / (float)IMG;
    float ui = ((float)oi + 0.5f) * scale - 0.5f;
    ui = fminf(fmaxf(ui, 0.f), (float)(w - 1));
    const int i0 = (int)ui;
    const int i1 = min(i0 + 1, w - 1);
    const float fi = ui - (float)i0;

    const float* r0 = x + (((size_t)b * 3 + ch) * IMG + (c0 + i0)) * IMG + c1;
    const float* r1 = x + (((size_t)b * 3 + ch) * IMG + (c0 + i1)) * IMG + c1;

    float4 v;
    float* vp = (float*)&v;
    #pragma unroll
    for (int q = 0; q < 4; ++q) {
        const int oj = oj0 + q;
        float uj = ((float)oj + 0.5f) * scale - 0.5f;
        uj = fminf(fmaxf(uj, 0.f), (float)(w - 1));
        const int j0 = (int)uj;
        const int j1 = min(j0 + 1, w - 1);
        const float fj = uj - (float)j0;

        const float p00 = __ldg(&r0[j0]);
        const float p01 = __ldg(&r0[j1]);
        const float p10 = __ldg(&r1[j0]);
        const float p11 = __ldg(&r1[j1]);

        vp[q] = (1.f - fi) * ((1.f - fj) * p00 + fj * p01)
              +        fi  * ((1.f - fj) * p10 + fj * p11);
    }

    *(float4*)(out + OFF_IMG + (((size_t)p * 3 + ch) * IMG + oi) * IMG + oj0) = v;
}

// ---------------------------------------------------------------------------
// Kernel D: logits = emb @ W + b.  grid = B_, block = 1024.
// 20 k-slices x 50 float4 output lanes; shared reduction.
// ---------------------------------------------------------------------------
__global__ void logits_kernel(const float* __restrict__ emb,
                              const float* __restrict__ W,
                              const float* __restrict__ bias,
                              float* __restrict__ out)
{
    __shared__ float4 sp[1000];
    const int b   = blockIdx.x;
    const int tid = threadIdx.x;
    const int slice = tid / 50;   // 0..19 (tid < 1000)
    const int o4    = tid % 50;   // float4 group of outputs

    float4 acc = make_float4(0.f, 0.f, 0.f, 0.f);
    if (tid < 1000) {
        const float* e = emb + b * 2048;
        #pragma unroll 4
        for (int k = slice; k < 2048; k += 20) {
            const float ek = __ldg(&e[k]);
            const float4 wv = __ldg((const float4*)(W + k * 200) + o4);
            acc.x = fmaf(ek, wv.x, acc.x);
            acc.y = fmaf(ek, wv.y, acc.y);
            acc.z = fmaf(ek, wv.z, acc.z);
            acc.w = fmaf(ek, wv.w, acc.w);
        }
        sp[tid] = acc;
    }
    __syncthreads();

    if (tid < 50) {
        float4 s = sp[tid];
        #pragma unroll
        for (int sl = 1; sl < 20; ++sl) {
            float4 q = sp[sl * 50 + tid];
            s.x += q.x; s.y += q.y; s.z += q.z; s.w += q.w;
        }
        const float4 bv = __ldg((const float4*)bias + tid);
        s.x += bv.x; s.y += bv.y; s.z += bv.z; s.w += bv.w;
        *(float4*)(out + OFF_LOG + b * 200 + tid * 4) = s;
    }
}

// ---------------------------------------------------------------------------
extern "C" void kernel_launch(void* const* d_in, const int* in_sizes, int n_in,
                              void* d_out, int out_size)
{
    const float* x      = (const float*)d_in[0];   // (8,3,448,448)
    const float* fm     = (const float*)d_in[1];   // (8,384,28,28)
    const float* emb    = (const float*)d_in[2];   // (8,2048)
    const float* W_cls  = (const float*)d_in[3];   // (2048,200)
    const float* b_cls  = (const float*)d_in[4];   // (200,)
    const int*   coords = (const int*)  d_in[5];   // (1595,4)
    float* out = (float*)d_out;

    csum_kernel  <<<dim3(B_, 8), 784>>>(fm);
    scores_kernel<<<B_, 1024>>>(out);
    nms_kernel   <<<B_ * NGROUP, 256>>>(out);
    crop_kernel  <<<dim3(196, 3, B_ * NPROP), 256>>>(x, coords, out);
    logits_kernel<<<B_, 1024>>>(emb, W_cls, b_cls, out);
}

// round 5
// speedup vs baseline: 4.2537x; 1.1754x over previous
#include <cuda_runtime.h>
#include <math.h>

// ---------------- problem constants ----------------
#define B_      8
#define FM      28
#define CH      384
#define IMG     448
#define NGROUP  3
#define NPROP   7          // 2 + 3 + 2
#define NTOT    1595       // 625 + 529 + 441
#define NSRC_MAX 20        // max source rows per 64-row output band (w=128)
#define HPITCH  452        // 448 + 4 pad: kills LDS bank conflicts between rows

__device__ __constant__ int   c_n[NGROUP]       = {25, 23, 21};   // FM - r + 1
__device__ __constant__ int   c_ng[NGROUP]      = {625, 529, 441};
__device__ __constant__ int   c_off[NGROUP]     = {0, 625, 1154};
__device__ __constant__ int   c_r[NGROUP]       = {4, 6, 8};
__device__ __constant__ int   c_nsel[NGROUP]    = {2, 3, 2};
__device__ __constant__ int   c_colbase[NGROUP] = {0, 2, 5};

// output layout (all float32, tuple order flattened)
#define OFF_IDX  0
#define OFF_PSC  (OFF_IDX + B_ * NPROP)                   // 56
#define OFF_ALL  (OFF_PSC + B_ * NPROP)                   // 112
#define OFF_IMG  (OFF_ALL + B_ * NTOT)                    // 12872
#define OFF_LOG  (OFF_IMG + B_ * NPROP * 3 * IMG * IMG)   // 33731144

// scratch
__device__ int    g_sel[B_ * NPROP];
__device__ float4 g_csum4[B_ * 8 * 196];   // per-(batch, channel-slice) partials, FM*FM = 196 float4

// ---------------------------------------------------------------------------
// Kernel A: channel-sum partials, float4. grid=(B_,8), block=196.
// Slice s sums channels [s*48, s*48+48).
// ---------------------------------------------------------------------------
__global__ void csum_kernel(const float* __restrict__ fm)
{
    const int b = blockIdx.x, s = blockIdx.y;
    const int tid = threadIdx.x;                 // 0..195
    const float4* p = (const float4*)(fm + ((size_t)b * CH + s * 48) * (FM * FM)) + tid;
    float4 acc = make_float4(0.f, 0.f, 0.f, 0.f);
    #pragma unroll 8
    for (int c = 0; c < 48; ++c) {
        float4 v = __ldg(&p[c * 196]);
        acc.x += v.x; acc.y += v.y; acc.z += v.z; acc.w += v.w;
    }
    g_csum4[(b * 8 + s) * 196 + tid] = acc;
}

// ---------------------------------------------------------------------------
// Kernel B: fused SAT + window scores + greedy NMS. grid = B_*3 (b,g), block=256.
// Each block rebuilds the 28x28 SAT (cheap), writes its group's all_scores
// slice, then runs NMS entirely from shared memory.
// ---------------------------------------------------------------------------
__global__ void scores_nms_kernel(float* __restrict__ out)
{
    const int blk = blockIdx.x;
    const int b = blk / NGROUP, g = blk % NGROUP;
    const int n = c_n[g], ng = c_ng[g], off = c_off[g];
    const int r = c_r[g], nsel = c_nsel[g], colbase = c_colbase[g];
    const int tid = threadIdx.x;
    const float NEG = -__int_as_float(0x7f800000);  // -inf

    __shared__ float s[FM * FM];
    __shared__ float sc[625];
    __shared__ float rv[256];
    __shared__ int   ri[256];
    __shared__ int   sel;
    __shared__ float selv;

    // channel-sum combine (8 slice partials)
    const float* cs = (const float*)&g_csum4[b * 8 * 196];
    for (int t = tid; t < FM * FM; t += 256) {
        float a = 0.f;
        #pragma unroll
        for (int sl = 0; sl < 8; ++sl) a += cs[sl * (FM * FM) + t];
        s[t] = a;
    }
    __syncthreads();
    if (tid < FM) {                                  // row prefix
        float a = 0.f;
        for (int j = 0; j < FM; ++j) { a += s[tid * FM + j]; s[tid * FM + j] = a; }
    }
    __syncthreads();
    if (tid < FM) {                                  // column prefix -> SAT
        float a = 0.f;
        for (int i = 0; i < FM; ++i) { a += s[i * FM + tid]; s[i * FM + tid] = a; }
    }
    __syncthreads();

    // window scores for this group (shared copy + global all_scores slice)
    float* dst = out + OFF_ALL + b * NTOT + off;
    const float inv = 1.f / (float)(r * r);
    for (int t = tid; t < ng; t += 256) {
        int i = t / n, j = t % n;
        int i2 = i + r - 1, j2 = j + r - 1;
        float sum = s[i2 * FM + j2];
        if (i > 0)          sum -= s[(i - 1) * FM + j2];
        if (j > 0)          sum -= s[i2 * FM + (j - 1)];
        if (i > 0 && j > 0) sum += s[(i - 1) * FM + (j - 1)];
        sum *= inv;
        sc[t] = sum;
        dst[t] = sum;
    }
    __syncthreads();

    // greedy NMS
    const float area = (16.f * r + 1.f) * (16.f * r + 1.f);
    const float side = 16.f * r;

    for (int k = 0; k < nsel; ++k) {
        float bv = NEG; int bi = 0x7fffffff;
        for (int t = tid; t < ng; t += 256) {
            float v = sc[t];
            if (v > bv) { bv = v; bi = t; }
        }
        rv[tid] = bv; ri[tid] = bi;
        __syncthreads();
        for (int st = 128; st > 0; st >>= 1) {
            if (tid < st) {
                float v = rv[tid + st]; int ii = ri[tid + st];
                if (v > rv[tid] || (v == rv[tid] && ii < ri[tid])) { rv[tid] = v; ri[tid] = ii; }
            }
            __syncthreads();
        }
        if (tid == 0) { sel = ri[0]; selv = rv[0]; }
        __syncthreads();
        const int si = sel;

        const float sx0 = (float)((si / n) * 16), sy0 = (float)((si % n) * 16);
        const float sx1 = sx0 + side, sy1 = sy0 + side;

        for (int t = tid; t < ng; t += 256) {
            float x0 = (float)((t / n) * 16), y0 = (float)((t % n) * 16);
            float x1 = x0 + side, y1 = y0 + side;
            float xx0 = fmaxf(x0, sx0), yy0 = fmaxf(y0, sy0);
            float xx1 = fminf(x1, sx1), yy1 = fminf(y1, sy1);
            float w = xx1 - xx0 + 1.f, h = yy1 - yy0 + 1.f;
            float inter = (w < 0.f || h < 0.f) ? 0.f : w * h;
            float iou = inter / (2.f * area - inter);
            if (iou > 0.25f) sc[t] = NEG;
        }
        __syncthreads();

        if (tid == 0) {
            int gi = off + si;
            out[OFF_IDX + b * NPROP + colbase + k] = (float)gi;
            out[OFF_PSC + b * NPROP + colbase + k] = selv;
            g_sel[b * NPROP + colbase + k] = gi;
        }
        __syncthreads();
    }
}

// ---------------------------------------------------------------------------
// Kernel C: separable crop+resize. grid = (7 bands, 3 ch, 56 props), block=224.
// Phase A: column LUT (j0, fj) + row LUT for this 64-row band.
// Phase B: horizontal resize of needed source rows into shared hrow.
// Phase C: vertical lerp, float4 LDS + float4 STG.
// ---------------------------------------------------------------------------
__global__ void crop_kernel(const float* __restrict__ x,
                            const int* __restrict__ coords,
                            float* __restrict__ out)
{
    __shared__ __align__(16) float hrow[NSRC_MAX * HPITCH];
    __shared__ int   jl_j0[IMG];
    __shared__ float jl_fj[IMG];
    __shared__ int   il_i0[64];
    __shared__ int   il_i1[64];
    __shared__ float il_fi[64];

    const int band = blockIdx.x;          // 0..6
    const int ch   = blockIdx.y;          // 0..2
    const int p    = blockIdx.z;          // 0..55
    const int tid  = threadIdx.x;         // 0..223

    const int col = p % NPROP;
    const int b   = p / NPROP;
    const int w   = (col < 2) ? 64 : ((col < 5) ? 96 : 128);
    const float scale = (float)w / (float)IMG;

    const int gi = g_sel[p];
    const int c0 = __ldg(&coords[4 * gi + 0]);
    const int c1 = __ldg(&coords[4 * gi + 1]);

    const int oi0 = band * 64;

    // band source-row range (mapping is monotone non-decreasing)
    float u_lo = fminf(fmaxf(((float)oi0 + 0.5f) * scale - 0.5f, 0.f), (float)(w - 1));
    float u_hi = fminf(fmaxf(((float)(oi0 + 63) + 0.5f) * scale - 0.5f, 0.f), (float)(w - 1));
    const int si_lo = (int)u_lo;
    const int si_hi = min((int)u_hi + 1, w - 1);
    const int nsrc  = si_hi - si_lo + 1;

    // Phase A: LUTs
    for (int oj = tid; oj < IMG; oj += 224) {
        float uj = ((float)oj + 0.5f) * scale - 0.5f;
        uj = fminf(fmaxf(uj, 0.f), (float)(w - 1));
        int j0 = (int)uj;
        jl_j0[oj] = j0;
        jl_fj[oj] = uj - (float)j0;
    }
    if (tid < 64) {
        float ui = ((float)(oi0 + tid) + 0.5f) * scale - 0.5f;
        ui = fminf(fmaxf(ui, 0.f), (float)(w - 1));
        int i0 = (int)ui;
        il_i0[tid] = i0 - si_lo;
        il_i1[tid] = min(i0 + 1, w - 1) - si_lo;
        il_fi[tid] = ui - (float)i0;
    }
    __syncthreads();

    // Phase B: horizontal resize of source rows [si_lo, si_hi] into hrow
    const float* srcbase = x + (((size_t)b * 3 + ch) * IMG + c0) * IMG + c1;
    const int total = nsrc * IMG;
    for (int idx = tid; idx < total; idx += 224) {
        const int sr = idx / IMG;          // 0..nsrc-1
        const int oj = idx - sr * IMG;
        const float* row = srcbase + (size_t)(si_lo + sr) * IMG;
        const int j0 = jl_j0[oj];
        const int j1 = min(j0 + 1, w - 1);
        const float fj = jl_fj[oj];
        const float v0 = __ldg(&row[j0]);
        const float v1 = __ldg(&row[j1]);
        hrow[sr * HPITCH + oj] = v0 + fj * (v1 - v0);
    }
    __syncthreads();

    // Phase C: vertical lerp, 4 px per thread per row
    const int cg   = tid % 112;            // column group: oj = cg*4
    const int half = tid / 112;            // 0 or 1
    float* obase = out + OFF_IMG + (((size_t)p * 3 + ch) * IMG + oi0) * IMG + cg * 4;

    #pragma unroll 4
    for (int rr = 0; rr < 32; ++rr) {
        const int ol = half * 32 + rr;     // 0..63
        const float fi = il_fi[ol];
        const float4 a = *(const float4*)&hrow[il_i0[ol] * HPITCH + cg * 4];
        const float4 c = *(const float4*)&hrow[il_i1[ol] * HPITCH + cg * 4];
        float4 v;
        v.x = a.x + fi * (c.x - a.x);
        v.y = a.y + fi * (c.y - a.y);
        v.z = a.z + fi * (c.z - a.z);
        v.w = a.w + fi * (c.w - a.w);
        *(float4*)(obase + (size_t)ol * IMG) = v;
    }
}

// ---------------------------------------------------------------------------
// Kernel D: logits = emb @ W + b.  grid = B_, block = 1024.
// 20 k-slices x 50 float4 output lanes; shared reduction.
// ---------------------------------------------------------------------------
__global__ void logits_kernel(const float* __restrict__ emb,
                              const float* __restrict__ W,
                              const float* __restrict__ bias,
                              float* __restrict__ out)
{
    __shared__ float4 sp[1000];
    const int b   = blockIdx.x;
    const int tid = threadIdx.x;
    const int slice = tid / 50;   // 0..19 (tid < 1000)
    const int o4    = tid % 50;

    float4 acc = make_float4(0.f, 0.f, 0.f, 0.f);
    if (tid < 1000) {
        const float* e = emb + b * 2048;
        #pragma unroll 4
        for (int k = slice; k < 2048; k += 20) {
            const float ek = __ldg(&e[k]);
            const float4 wv = __ldg((const float4*)(W + k * 200) + o4);
            acc.x = fmaf(ek, wv.x, acc.x);
            acc.y = fmaf(ek, wv.y, acc.y);
            acc.z = fmaf(ek, wv.z, acc.z);
            acc.w = fmaf(ek, wv.w, acc.w);
        }
        sp[tid] = acc;
    }
    __syncthreads();

    if (tid < 50) {
        float4 s = sp[tid];
        #pragma unroll
        for (int sl = 1; sl < 20; ++sl) {
            float4 q = sp[sl * 50 + tid];
            s.x += q.x; s.y += q.y; s.z += q.z; s.w += q.w;
        }
        const float4 bv = __ldg((const float4*)bias + tid);
        s.x += bv.x; s.y += bv.y; s.z += bv.z; s.w += bv.w;
        *(float4*)(out + OFF_LOG + b * 200 + tid * 4) = s;
    }
}

// ---------------------------------------------------------------------------
extern "C" void kernel_launch(void* const* d_in, const int* in_sizes, int n_in,
                              void* d_out, int out_size)
{
    const float* x      = (const float*)d_in[0];   // (8,3,448,448)
    const float* fm     = (const float*)d_in[1];   // (8,384,28,28)
    const float* emb    = (const float*)d_in[2];   // (8,2048)
    const float* W_cls  = (const float*)d_in[3];   // (2048,200)
    const float* b_cls  = (const float*)d_in[4];   // (200,)
    const int*   coords = (const int*)  d_in[5];   // (1595,4)
    float* out = (float*)d_out;

    csum_kernel      <<<dim3(B_, 8), 196>>>(fm);
    logits_kernel    <<<B_, 1024>>>(emb, W_cls, b_cls, out);  // independent; overlaps tail
    scores_nms_kernel<<<B_ * NGROUP, 256>>>(out);
    crop_kernel      <<<dim3(7, 3, B_ * NPROP), 224>>>(x, coords, out);
}